// round 10
// baseline (speedup 1.0000x reference)
#include <cuda_runtime.h>
#include <cuda_fp16.h>

// Problem constants (fixed by the dataset; guarded at runtime).
#define NN 100000
#define EE 3200000
#define FF 128
#define F4 (FF / 4)   // 32 float4 per feature row
#define NWARPS 8      // warps per block (256 threads)

// ---------------- static scratch (no allocations; zero-init at load) ------
__device__ int    g_deg[NN];                  // re-zeroed each call (phase 4)
__device__ float  g_dinv[NN];
__device__ float  g_sqd[NN];
__device__ int    g_rowptr[NN + 1];
__device__ int    g_curptr[NN];
__device__ int    g_scan[NN];
__device__ int    g_part[128];
__device__ int    g_meta[EE];                 // BYTE offset of src row (= row*256)
__device__ float4 g_px[NN * F4];              // X' = Dinv*x (fp32 master, P0)
__device__ float4 g_pa[NN * F4];              // fp32 P ping-pong
__device__ float4 g_pb[NN * F4];
__device__ uint2  g_h16a[NN * F4];            // fp16 gather rows (256 B/node)
__device__ uint2  g_h16b[NN * F4];

// ---------------- software grid barrier (all blocks co-resident) ----------
__device__ unsigned g_bin = 0;                 // arrival counter
__device__ volatile unsigned g_bph = 0;        // generation (monotonic)

__device__ __forceinline__ void gbar(unsigned nblk) {
    __syncthreads();
    if (threadIdx.x == 0) {
        __threadfence();                       // release my stores
        unsigned gen = g_bph;                  // stable: barrier not yet complete
        if (atomicAdd(&g_bin, 1u) == nblk - 1u) {
            g_bin = 0;                         // all arrived; safe to reset
            __threadfence();
            g_bph = gen + 1u;                  // release
        } else {
            while (g_bph == gen) { __nanosleep(128); }
        }
        __threadfence();                       // acquire side
    }
    __syncthreads();
}

// ---------------- SpMM phase (fp16 .cg gather, 2 edges/iter) --------------
// Scaled space: P'_i = Dinv * P_i; gather is an unweighted sum over in-edges.
//   step 1:  P'_1 = d2*S;              acc = mf0*X' + w1*P'_1
//   step>=2: P'_i = 2*d2*S - P'_{i-2}; acc += wi*P'_i
//   step K:  out = acc * sqrt(deg); isolated nodes handled analytically.
__device__ __forceinline__ void spmm_phase(
    int step, int K, int n, int gw, int TW, int lane, int* smeta_w,
    const float4* __restrict__ x4, const float* __restrict__ mf,
    const float* __restrict__ lap, float4* __restrict__ acc)
{
    const char* h16 = (const char*)(((step - 1) & 1) ? g_h16b : g_h16a);
    uint2* pout16   = (step & 1) ? g_h16b : g_h16a;
    float4* pout    = (step & 1) ? g_pa : g_pb;
    const float4* pprev2 =
        (step <= 2) ? (const float4*)g_px
                    : ((step & 1) ? (const float4*)g_pa : (const float4*)g_pb);

    float wi = lap[step - 1] * mf[step];
    float w0 = mf[0];
    int half = lane >> 4;
    const char* hl = h16 + ((lane & 15) << 4);   // lane's 16-byte slice
    const unsigned FULL = 0xffffffffu;

    for (int c = gw; c < n; c += TW) {
        int start = g_rowptr[c];
        int end   = g_rowptr[c + 1];

        float a0=0.f,a1=0.f,a2=0.f,a3=0.f,a4=0.f,a5=0.f,a6=0.f,a7=0.f;

        for (int base = start; base < end; base += 32) {
            int m = end - base;
            if (m > 32) m = 32;
            if (lane < m) smeta_w[lane] = g_meta[base + lane];
            __syncwarp();
            int npair = m >> 1;
            #pragma unroll 4
            for (int k = 0; k < npair; k++) {
                int off = smeta_w[2 * k + half];
                uint4 hv = __ldcg((const uint4*)(hl + off));   // L2-only: fresh
                float2 f0 = __half22float2(*(const __half2*)&hv.x);
                float2 f1 = __half22float2(*(const __half2*)&hv.y);
                float2 f2 = __half22float2(*(const __half2*)&hv.z);
                float2 f3 = __half22float2(*(const __half2*)&hv.w);
                a0 += f0.x; a1 += f0.y; a2 += f1.x; a3 += f1.y;
                a4 += f2.x; a5 += f2.y; a6 += f3.x; a7 += f3.y;
            }
            if ((m & 1) && half == 0) {
                int off = smeta_w[m - 1];
                uint4 hv = __ldcg((const uint4*)(hl + off));
                float2 f0 = __half22float2(*(const __half2*)&hv.x);
                float2 f1 = __half22float2(*(const __half2*)&hv.y);
                float2 f2 = __half22float2(*(const __half2*)&hv.z);
                float2 f3 = __half22float2(*(const __half2*)&hv.w);
                a0 += f0.x; a1 += f0.y; a2 += f1.x; a3 += f1.y;
                a4 += f2.x; a5 += f2.y; a6 += f3.x; a7 += f3.y;
            }
            __syncwarp();
        }

        // Combine edge-halves, then redistribute so lane L owns float4 #L.
        a0 += __shfl_xor_sync(FULL, a0, 16);
        a1 += __shfl_xor_sync(FULL, a1, 16);
        a2 += __shfl_xor_sync(FULL, a2, 16);
        a3 += __shfl_xor_sync(FULL, a3, 16);
        a4 += __shfl_xor_sync(FULL, a4, 16);
        a5 += __shfl_xor_sync(FULL, a5, 16);
        a6 += __shfl_xor_sync(FULL, a6, 16);
        a7 += __shfl_xor_sync(FULL, a7, 16);

        int src = lane >> 1;
        float c0 = __shfl_sync(FULL, a0, src);
        float c1 = __shfl_sync(FULL, a1, src);
        float c2 = __shfl_sync(FULL, a2, src);
        float c3 = __shfl_sync(FULL, a3, src);
        float c4 = __shfl_sync(FULL, a4, src);
        float c5 = __shfl_sync(FULL, a5, src);
        float c6 = __shfl_sync(FULL, a6, src);
        float c7 = __shfl_sync(FULL, a7, src);
        bool odd = (lane & 1);
        float sx = odd ? c4 : c0;
        float sy = odd ? c5 : c1;
        float sz = odd ? c6 : c2;
        float sw = odd ? c7 : c3;

        int idx = c * F4 + lane;
        float dinv = g_dinv[c];
        float d2 = dinv * dinv;

        float4 p, a;
        if (step == 1) {
            float4 xp = pprev2[idx];              // X'
            p.x = d2 * sx; p.y = d2 * sy; p.z = d2 * sz; p.w = d2 * sw;
            a.x = w0 * xp.x + wi * p.x;
            a.y = w0 * xp.y + wi * p.y;
            a.z = w0 * xp.z + wi * p.z;
            a.w = w0 * xp.w + wi * p.w;
        } else {
            float4 p2 = pprev2[idx];              // own node: SM-local history
            float td2 = 2.f * d2;
            p.x = td2 * sx - p2.x;
            p.y = td2 * sy - p2.y;
            p.z = td2 * sz - p2.z;
            p.w = td2 * sw - p2.w;
            a = acc[idx];
            a.x += wi * p.x;
            a.y += wi * p.y;
            a.z += wi * p.z;
            a.w += wi * p.w;
        }

        if (step < K) {
            acc[idx] = a;
            if (step + 2 <= K) pout[idx] = p;     // fp32 master only if reread
            __half2 h01 = __floats2half2_rn(p.x, p.y);
            __half2 h23 = __floats2half2_rn(p.z, p.w);
            uint2 u;
            u.x = *(unsigned int*)&h01;
            u.y = *(unsigned int*)&h23;
            pout16[idx] = u;
        } else {
            float sd = g_sqd[c];
            if (sd > 0.f) {
                a.x *= sd; a.y *= sd; a.z *= sd; a.w *= sd;
                acc[idx] = a;
            } else {
                // isolated node: P_{2j} = (-1)^j x, P_odd = 0
                float cE = mf[0];
                float sgn = -1.f;
                for (int j = 2; j <= K; j += 2) {
                    cE += sgn * lap[j - 1] * mf[j];
                    sgn = -sgn;
                }
                float4 xv = x4[idx];
                xv.x *= cE; xv.y *= cE; xv.z *= cE; xv.w *= cE;
                acc[idx] = xv;
            }
        }
    }
}

// ---------------- the single persistent kernel ----------------------------
__global__ void __launch_bounds__(256)
mega_k(const int* __restrict__ rowp, const int* __restrict__ colp,
       const float4* __restrict__ x4, const float* __restrict__ mf,
       const float* __restrict__ lap, float4* __restrict__ out,
       int E, int K, int n) {
    __shared__ int smeta[NWARPS][32];
    __shared__ int wsum[NWARPS];

    unsigned nblk = gridDim.x;
    int tid  = threadIdx.x;
    int lane = tid & 31;
    int w    = tid >> 5;
    int gid  = blockIdx.x * 256 + tid;
    int gstride = nblk * 256;
    int gw   = blockIdx.x * NWARPS + w;       // global warp id (node mapping)
    int TW   = nblk * NWARPS;
    const unsigned FULL = 0xffffffffu;

    // ---- phase 1: in-degree histogram ----
    {
        int E4 = E >> 2;
        const int4* col4 = (const int4*)colp;
        for (int t = gid; t < E4; t += gstride) {
            int4 c = __ldg(&col4[t]);
            atomicAdd(&g_deg[c.x], 1);
            atomicAdd(&g_deg[c.y], 1);
            atomicAdd(&g_deg[c.z], 1);
            atomicAdd(&g_deg[c.w], 1);
        }
        for (int e = E4 * 4 + gid; e < E; e += gstride)
            atomicAdd(&g_deg[colp[e]], 1);
    }
    gbar(nblk);

    // ---- phase 2: chunked scan (1024 elems/chunk, 4/thread) + dinv/sqd ----
    {
        int nchunks = (n + 1023) >> 10;
        for (int chunk = blockIdx.x; chunk < nchunks; chunk += nblk) {
            int i0 = (chunk << 10) + tid * 4;
            int v[4];
            #pragma unroll
            for (int j = 0; j < 4; j++) {
                int i = i0 + j;
                int d = (i < n) ? g_deg[i] : 0;
                v[j] = d;
                if (i < n) {
                    g_dinv[i] = (d > 0) ? rsqrtf((float)d) : 0.0f;
                    g_sqd[i]  = (d > 0) ? sqrtf((float)d)  : 0.0f;
                }
            }
            int s = v[0] + v[1] + v[2] + v[3];
            int sc = s;
            #pragma unroll
            for (int o = 1; o < 32; o <<= 1) {
                int t = __shfl_up_sync(FULL, sc, o);
                if (lane >= o) sc += t;
            }
            if (lane == 31) wsum[w] = sc;
            __syncthreads();
            if (w == 0) {
                int ws = (lane < NWARPS) ? wsum[lane] : 0;
                #pragma unroll
                for (int o = 1; o < NWARPS; o <<= 1) {
                    int t = __shfl_up_sync(FULL, ws, o);
                    if (lane >= o) ws += t;
                }
                if (lane < NWARPS) wsum[lane] = ws;
            }
            __syncthreads();
            int tbase = ((w > 0) ? wsum[w - 1] : 0) + sc - s;  // thread-exclusive
            int run = tbase;
            #pragma unroll
            for (int j = 0; j < 4; j++) {
                run += v[j];
                int i = i0 + j;
                if (i < n) g_scan[i] = run;                    // chunk-inclusive
            }
            if (tid == 0) g_part[chunk] = wsum[NWARPS - 1];    // chunk total
            __syncthreads();
        }
    }
    gbar(nblk);

    // ---- phase 3: rowptr/curptr + prescale X' (fp32 + fp16 buffer 0) ----
    {
        for (int i = gid; i < n; i += gstride) {
            int blk = i >> 10;
            int pre = 0;
            for (int b = 0; b < blk; b++) pre += g_part[b];    // L1-cached
            int excl = g_scan[i] - g_deg[i] + pre;
            g_rowptr[i] = excl;
            g_curptr[i] = excl;
        }
        if (gid == 0) g_rowptr[n] = E;

        int total = n * F4;
        for (int j = gid; j < total; j += gstride) {
            float s = g_dinv[j >> 5];
            float4 v = x4[j];
            v.x *= s; v.y *= s; v.z *= s; v.w *= s;
            g_px[j] = v;
            __half2 h01 = __floats2half2_rn(v.x, v.y);
            __half2 h23 = __floats2half2_rn(v.z, v.w);
            uint2 u;
            u.x = *(unsigned int*)&h01;
            u.y = *(unsigned int*)&h23;
            g_h16a[j] = u;
        }
    }
    gbar(nblk);

    // ---- phase 4: scatter (byte offsets) + re-zero deg for next call ----
    {
        int E4 = E >> 2;
        const int4* col4 = (const int4*)colp;
        const int4* row4 = (const int4*)rowp;
        for (int t = gid; t < E4; t += gstride) {
            int4 c = __ldg(&col4[t]);
            int4 r = __ldg(&row4[t]);
            int p0 = atomicAdd(&g_curptr[c.x], 1);
            int p1 = atomicAdd(&g_curptr[c.y], 1);
            int p2 = atomicAdd(&g_curptr[c.z], 1);
            int p3 = atomicAdd(&g_curptr[c.w], 1);
            g_meta[p0] = r.x << 8;
            g_meta[p1] = r.y << 8;
            g_meta[p2] = r.z << 8;
            g_meta[p3] = r.w << 8;
        }
        for (int e = E4 * 4 + gid; e < E; e += gstride) {
            int pos = atomicAdd(&g_curptr[colp[e]], 1);
            g_meta[pos] = rowp[e] << 8;
        }
        for (int j = gid; j < n; j += gstride) g_deg[j] = 0;
    }

    // ---- phases 5..: K SpMM steps with grid barrier between ----
    for (int step = 1; step <= K; step++) {
        gbar(nblk);
        spmm_phase(step, K, n, gw, TW, lane, smeta[w], x4, mf, lap, out);
    }
}

// ---------------- launch ----------------
extern "C" void kernel_launch(void* const* d_in, const int* in_sizes, int n_in,
                              void* d_out, int out_size) {
    const float* x   = (const float*)d_in[0];
    const float* mf  = (const float*)d_in[1];   // (1, K+1, 1)
    const float* lap = (const float*)d_in[2];   // (K+1,)
    const int*   ei  = (const int*)d_in[3];     // (2, E) row-major

    int E = in_sizes[3] / 2;
    int K = in_sizes[2] - 1;
    int n = in_sizes[0] / FF;
    if (n > NN) n = NN;
    if (E > EE) E = EE;

    const int* rowp = ei;
    const int* colp = ei + E;

    // Size grid for guaranteed co-residency (deterministic per device).
    int dev = 0;
    cudaGetDevice(&dev);
    int smCount = 0;
    cudaDeviceGetAttribute(&smCount, cudaDevAttrMultiProcessorCount, dev);
    int occ = 0;
    cudaOccupancyMaxActiveBlocksPerMultiprocessor(&occ, mega_k, 256, 0);
    if (occ < 1) occ = 1;
    int nblk = smCount * occ;

    mega_k<<<nblk, 256>>>(rowp, colp, (const float4*)x, mf, lap,
                          (float4*)d_out, E, K, n);
}